// round 16
// baseline (speedup 1.0000x reference)
#include <cuda_runtime.h>
#include <cuda_bf16.h>

// SHEmbed, quad-cooperative gather (contiguous 48B slices), 2 rays per thread,
// L2 evict_last policy on table gathers, evict-first streams, and a register
// cap (<=40 via launch_bounds min-blocks) to recover occupancy.

#define SH_W 1024

__device__ __forceinline__ float clamp01(float v) {
    return fminf(fmaxf(v, 0.0f), 1.0f);
}

__device__ __forceinline__ float4 ldg_keep(const float4* p, unsigned long long pol) {
    float4 v;
    asm("ld.global.nc.L2::cache_hint.v4.f32 {%0,%1,%2,%3}, [%4], %5;"
        : "=f"(v.x), "=f"(v.y), "=f"(v.z), "=f"(v.w) : "l"(p), "l"(pol));
    return v;
}

__global__ __launch_bounds__(256, 6)   // cap regs at 40 -> 48 warps/SM ceiling
void SHEmbed_kernel(const int* __restrict__ yi,
                    const int* __restrict__ xi,
                    const float* __restrict__ dirs,
                    const float4* __restrict__ sh,   // sh_data viewed as float4[H*W*12]
                    float* __restrict__ out,
                    int n)
{
    int t = blockIdx.x * blockDim.x + threadIdx.x;
    int q = t >> 2;          // ray-pair index
    int p = t & 3;           // quad lane: coefficient group 4p..4p+3
    int r0 = q * 2;
    if (r0 >= n) return;
    int r1 = (r0 + 1 < n) ? (r0 + 1) : r0;   // clamp tail

    unsigned long long pol;
    asm("createpolicy.fractional.L2::evict_last.b64 %0, 1.0;" : "=l"(pol));

    // ---- front-batch ALL independent loads for both rays (streaming: evict-first) ----
    int y0 = __ldcs(yi + r0), x0 = __ldcs(xi + r0);
    int y1 = __ldcs(yi + r1), x1 = __ldcs(xi + r1);

    float dx0 = __ldcs(dirs + 3 * r0 + 0);
    float dy0 = __ldcs(dirs + 3 * r0 + 1);
    float dz0 = __ldcs(dirs + 3 * r0 + 2);
    float dx1 = __ldcs(dirs + 3 * r1 + 0);
    float dy1 = __ldcs(dirs + 3 * r1 + 1);
    float dz1 = __ldcs(dirs + 3 * r1 + 2);

    unsigned b0i = ((unsigned)y0 * SH_W + (unsigned)x0) * 12u + (unsigned)(3 * p);
    unsigned b1i = ((unsigned)y1 * SH_W + (unsigned)x1) * 12u + (unsigned)(3 * p);

    // ---- gather: keep in L2 for duplicate-record reuse ----
    float4 a0 = ldg_keep(sh + b0i + 0, pol);
    float4 a1 = ldg_keep(sh + b0i + 1, pol);
    float4 a2 = ldg_keep(sh + b0i + 2, pol);
    float4 c0 = ldg_keep(sh + b1i + 0, pol);
    float4 c1 = ldg_keep(sh + b1i + 1, pol);
    float4 c2 = ldg_keep(sh + b1i + 2, pol);

    // ---- unit directions (overlap gather latency) ----
    float ri0 = rsqrtf(dx0 * dx0 + dy0 * dy0 + dz0 * dz0 + 1e-28f);
    float nx0 = dx0 * ri0, ny0 = dy0 * ri0, nz0 = dz0 * ri0;
    float ri1 = rsqrtf(dx1 * dx1 + dy1 * dy1 + dz1 * dz1 + 1e-28f);
    float nx1 = dx1 * ri1, ny1 = dy1 * ri1, nz1 = dz1 * ri1;

    float xx0 = nx0 * nx0, yy0 = ny0 * ny0, zz0 = nz0 * nz0;
    float xx1 = nx1 * nx1, yy1 = ny1 * ny1, zz1 = nz1 * nz1;

    // ---- per-lane weights for coeffs 4p..4p+3, both rays ----
    float w00, w01, w02, w03;   // ray0
    float w10, w11, w12, w13;   // ray1
    switch (p) {
    case 0:
        w00 =  0.28209479177387814f;
        w01 = -0.4886025119029199f * ny0;
        w02 =  0.4886025119029199f * nz0;
        w03 = -0.4886025119029199f * nx0;
        w10 =  0.28209479177387814f;
        w11 = -0.4886025119029199f * ny1;
        w12 =  0.4886025119029199f * nz1;
        w13 = -0.4886025119029199f * nx1;
        break;
    case 1:
        w00 =  1.0925484305920792f * nx0 * ny0;
        w01 = -1.0925484305920792f * ny0 * nz0;
        w02 =  0.31539156525252005f * (3.0f * zz0 - 1.0f);
        w03 = -1.0925484305920792f * nx0 * nz0;
        w10 =  1.0925484305920792f * nx1 * ny1;
        w11 = -1.0925484305920792f * ny1 * nz1;
        w12 =  0.31539156525252005f * (3.0f * zz1 - 1.0f);
        w13 = -1.0925484305920792f * nx1 * nz1;
        break;
    case 2:
        w00 =  0.5462742152960396f * (xx0 - yy0);
        w01 = -0.5900435899266435f * ny0 * (3.0f * xx0 - yy0);
        w02 =  2.890611442640554f  * nx0 * ny0 * nz0;
        w03 = -0.4570457994644658f * ny0 * (5.0f * zz0 - 1.0f);
        w10 =  0.5462742152960396f * (xx1 - yy1);
        w11 = -0.5900435899266435f * ny1 * (3.0f * xx1 - yy1);
        w12 =  2.890611442640554f  * nx1 * ny1 * nz1;
        w13 = -0.4570457994644658f * ny1 * (5.0f * zz1 - 1.0f);
        break;
    default:
        w00 =  0.3731763325901154f * nz0 * (5.0f * zz0 - 3.0f);
        w01 = -0.4570457994644658f * nx0 * (5.0f * zz0 - 1.0f);
        w02 =  1.4453057213202769f * nz0 * (xx0 - yy0);
        w03 = -0.5900435899266435f * nx0 * (xx0 - 3.0f * yy0);
        w10 =  0.3731763325901154f * nz1 * (5.0f * zz1 - 3.0f);
        w11 = -0.4570457994644658f * nx1 * (5.0f * zz1 - 1.0f);
        w12 =  1.4453057213202769f * nz1 * (xx1 - yy1);
        w13 = -0.5900435899266435f * nx1 * (xx1 - 3.0f * yy1);
        break;
    }

    // ---- partial dots (chunk layout: {c0r,c0g,c0b,c1r}{c1g,c1b,c2r,c2g}{c2b,c3r,c3g,c3b}) ----
    float cr0 = w00 * a0.x + w01 * a0.w + w02 * a1.z + w03 * a2.y;
    float cg0 = w00 * a0.y + w01 * a1.x + w02 * a1.w + w03 * a2.z;
    float cb0 = w00 * a0.z + w01 * a1.y + w02 * a2.x + w03 * a2.w;
    float cr1 = w10 * c0.x + w11 * c0.w + w12 * c1.z + w13 * c2.y;
    float cg1 = w10 * c0.y + w11 * c1.x + w12 * c1.w + w13 * c2.z;
    float cb1 = w10 * c0.z + w11 * c1.y + w12 * c2.x + w13 * c2.w;

    // ---- quad reductions ----
    const unsigned m = 0xffffffffu;
    cr0 += __shfl_xor_sync(m, cr0, 1);  cr0 += __shfl_xor_sync(m, cr0, 2);
    cg0 += __shfl_xor_sync(m, cg0, 1);  cg0 += __shfl_xor_sync(m, cg0, 2);
    cb0 += __shfl_xor_sync(m, cb0, 1);  cb0 += __shfl_xor_sync(m, cb0, 2);
    cr1 += __shfl_xor_sync(m, cr1, 1);  cr1 += __shfl_xor_sync(m, cr1, 2);
    cg1 += __shfl_xor_sync(m, cg1, 1);  cg1 += __shfl_xor_sync(m, cg1, 2);
    cb1 += __shfl_xor_sync(m, cb1, 1);  cb1 += __shfl_xor_sync(m, cb1, 2);

    // ---- clamp + store (streaming, evict-first): lane p<3 writes channel p ----
    if (p < 3) {
        float v0s = (p == 0) ? cr0 : (p == 1) ? cg0 : cb0;
        __stcs(out + 3 * r0 + p, clamp01(v0s));
        if (r0 + 1 < n) {
            float v1s = (p == 0) ? cr1 : (p == 1) ? cg1 : cb1;
            __stcs(out + 3 * r1 + p, clamp01(v1s));
        }
    }
}

extern "C" void kernel_launch(void* const* d_in, const int* in_sizes, int n_in,
                              void* d_out, int out_size)
{
    const int*    y    = (const int*)d_in[0];
    const int*    x    = (const int*)d_in[1];
    const float*  dirs = (const float*)d_in[2];
    const float4* sh   = (const float4*)d_in[3];
    float*        out  = (float*)d_out;

    int n = in_sizes[0];
    int threads = 256;
    long long pairs = ((long long)n + 1) / 2;
    long long total = 4LL * pairs;
    int blocks = (int)((total + threads - 1) / threads);
    SHEmbed_kernel<<<blocks, threads>>>(y, x, dirs, sh, out, n);
}